// round 13
// baseline (speedup 1.0000x reference)
#include <cuda_runtime.h>
#include <cuda_fp16.h>
#include <cstdint>

#define BATCH 64
#define NCAP  16
#define DCAP  64
#define NIN   512
#define DIN   1024

// ---------------- scratch (allocation-free: __device__ globals) ----------------
__device__ __half g_xh[(size_t)BATCH * NIN * DIN];       // 64 MB, x f16 [b][j][k]
__device__ __half g_wh16[(size_t)DIN * NCAP * DCAP];     // 2 MB, W f16 [k][n]
__device__ float  g_xsump[8][BATCH][DIN];                // 2 MB, partial x sums over j
__device__ __half g_t16[(size_t)BATCH * NCAP * DIN];     // 2 MB, t f16 [b][i][k]
__device__ float  g_ypart[8][BATCH][NCAP][DIN];          // 32 MB, y partials

// ---------------- helpers ----------------
__device__ __forceinline__ uint32_t smem_u32(const void* p) {
    uint32_t a;
    asm("{ .reg .u64 t; cvta.to.shared.u64 t, %1; cvt.u32.u64 %0, t; }" : "=r"(a) : "l"(p));
    return a;
}
__device__ __forceinline__ void cp16(uint32_t dst, const void* src) {
    asm volatile("cp.async.cg.shared.global [%0], [%1], 16;\n" :: "r"(dst), "l"(src));
}
__device__ __forceinline__ void cp_commit() { asm volatile("cp.async.commit_group;\n" ::: "memory"); }

__device__ __forceinline__ void hmma(float* d, const uint32_t* a, const uint32_t* b) {
    asm volatile(
        "mma.sync.aligned.m16n8k16.row.col.f32.f16.f16.f32 "
        "{%0,%1,%2,%3}, {%4,%5,%6,%7}, {%8,%9}, {%0,%1,%2,%3};\n"
        : "+f"(d[0]), "+f"(d[1]), "+f"(d[2]), "+f"(d[3])
        : "r"(a[0]), "r"(a[1]), "r"(a[2]), "r"(a[3]), "r"(b[0]), "r"(b[1]));
}
__device__ __forceinline__ void ldsm_x4(uint32_t* r, uint32_t addr) {
    asm volatile("ldmatrix.sync.aligned.m8n8.x4.shared.b16 {%0,%1,%2,%3}, [%4];"
                 : "=r"(r[0]), "=r"(r[1]), "=r"(r[2]), "=r"(r[3]) : "r"(addr));
}
__device__ __forceinline__ void ldsm_x2t(uint32_t* r, uint32_t addr) {
    asm volatile("ldmatrix.sync.aligned.m8n8.x2.trans.shared.b16 {%0,%1}, [%2];"
                 : "=r"(r[0]), "=r"(r[1]) : "r"(addr));
}

// ---------------- prep: W f32 -> f16 ----------------
__global__ __launch_bounds__(256) void wh16_kernel(const float* __restrict__ W) {
    const size_t n4 = (size_t)DIN * 1024 / 4;
    for (size_t e = (size_t)blockIdx.x * blockDim.x + threadIdx.x; e < n4;
         e += (size_t)gridDim.x * blockDim.x) {
        float4 v = ((const float4*)W)[e];
        __half2* dst = (__half2*)g_wh16 + e * 2;
        dst[0] = __floats2half2_rn(v.x, v.y);
        dst[1] = __floats2half2_rn(v.z, v.w);
    }
}

// ---------------- pass0: xsum partials + x -> f16 ----------------
__global__ __launch_bounds__(256) void pass0(const float* __restrict__ X) {
    const int c = blockIdx.x, b = blockIdx.y, tid = threadIdx.x;
    const size_t rowbase = ((size_t)b * NIN + c * 64) * DIN;
    const float4* xp = (const float4*)(X + rowbase) + tid;
    uint2* xh = (uint2*)(g_xh + rowbase) + tid;
    float4 a = make_float4(0.f, 0.f, 0.f, 0.f);
#pragma unroll 4
    for (int j = 0; j < 64; j++) {
        const float4 v = xp[j * (DIN / 4)];
        a.x += v.x; a.y += v.y; a.z += v.z; a.w += v.w;
        const __half2 h0 = __floats2half2_rn(v.x, v.y);
        const __half2 h1 = __floats2half2_rn(v.z, v.w);
        uint2 u;
        u.x = *(const unsigned*)&h0;
        u.y = *(const unsigned*)&h1;
        xh[j * (DIN / 4)] = u;
    }
    ((float4*)g_xsump[c][b])[tid] = a;
}

// ---------------- kA2: y -> z = y@W_i -> out = squash(z) -> t16 = W_i@out ----------------
// grid (16 i, 8 bgroup of 8) = 128 CTAs = one full wave.
#define KAB 8
#define KA_Y_OFF (DIN * DCAP * 2)                    // 131072
#define KA_Z_OFF (KA_Y_OFF + KAB * DIN * 4)          // +32768
#define KA_O_OFF (KA_Z_OFF + 8 * KAB * 64 * 4)       // +16384
#define KA_SMEM  (KA_O_OFF + KAB * 32 * 8)           // 182272

__global__ __launch_bounds__(512) void kA2(float* __restrict__ d_out, int stage) {
    extern __shared__ char smb[];
    const uint32_t sb = smem_u32(smb);
    __half*  Wh   = (__half*)smb;                        // [1024][64]
    float*   y_s  = (float*)(smb + KA_Y_OFF);            // [8][1024]
    float*   zred = (float*)(smb + KA_Z_OFF);            // [8 ks][8 bl][64]
    float2*  out2 = (float2*)(smb + KA_O_OFF);           // [8][32]

    const int i = blockIdx.x, bg = blockIdx.y, tid = threadIdx.x;
    const int b0 = bg * KAB;
    const int lane = tid & 31;

    {
        const __half* src = g_wh16 + i * 64;
#pragma unroll 4
        for (int e = tid; e < 8192; e += 512) {
            const int k = e >> 3, c = e & 7;
            cp16(sb + k * 128 + c * 16, src + (size_t)k * 1024 + c * 8);
        }
        cp_commit();
    }

    for (int e = tid; e < KAB * DIN; e += 512) {
        const int bl = e >> 10, k = e & 1023;
        float v = 0.f;
        if (stage == 0) {
#pragma unroll
            for (int p = 0; p < 8; p++) v += g_xsump[p][b0 + bl][k];
            v *= (1.f / 16.f);
        } else {
#pragma unroll
            for (int p = 0; p < 8; p++) v += g_ypart[p][b0 + bl][i][k];
        }
        y_s[e] = v;
    }
    asm volatile("cp.async.wait_group 0;\n" ::: "memory");
    __syncthreads();

    // z: thread (ks = tid>>6, d = tid&63), 8 batches
    {
        const int ks = tid >> 6, d = tid & 63;
        float acc[KAB];
#pragma unroll
        for (int q = 0; q < KAB; q++) acc[q] = 0.f;
        const __half* wp = Wh + (size_t)(ks * 128) * 64 + d;
#pragma unroll 4
        for (int k2 = 0; k2 < 128; k2++) {
            const float w = __half2float(wp[k2 * 64]);
            const int k = ks * 128 + k2;
#pragma unroll
            for (int bl = 0; bl < KAB; bl++)
                acc[bl] = fmaf(y_s[bl * 1024 + k], w, acc[bl]);
        }
#pragma unroll
        for (int bl = 0; bl < KAB; bl++) zred[(ks * KAB + bl) * 64 + d] = acc[bl];
    }
    __syncthreads();

    if (tid < KAB * 32) {
        const int bl = tid >> 5;
        float za = 0.f, zb = 0.f;
#pragma unroll
        for (int p = 0; p < 8; p++) {
            za += zred[(p * KAB + bl) * 64 + 2 * lane];
            zb += zred[(p * KAB + bl) * 64 + 2 * lane + 1];
        }
        float sq = za * za + zb * zb;
#pragma unroll
        for (int o = 16; o; o >>= 1) sq += __shfl_xor_sync(0xffffffffu, sq, o);
        const float inv = 1.0f / sqrtf(sq + 1e-7f);
        const float ox = za * inv, oy = zb * inv;
        out2[bl * 32 + lane] = make_float2(ox, oy);
        if (stage == 2) {
            float2* dp = (float2*)(d_out + ((size_t)(b0 + bl) * NCAP + i) * DCAP);
            dp[lane] = make_float2(ox, oy);
        }
    }
    __syncthreads();
    if (stage == 2) return;

    const __half2* Wh2 = (const __half2*)Wh;
#pragma unroll
    for (int r = 0; r < 2; r++) {
        const int k = r * 512 + tid;
        const __half2* wk = Wh2 + (size_t)k * 32;
        float ta[KAB];
#pragma unroll
        for (int q = 0; q < KAB; q++) ta[q] = 0.f;
#pragma unroll 4
        for (int qw = 0; qw < 32; qw++) {
            const int m = (lane + qw) & 31;
            const float2 wv = __half22float2(wk[m]);
#pragma unroll
            for (int bl = 0; bl < KAB; bl++) {
                const float2 o = out2[bl * 32 + m];
                ta[bl] = fmaf(wv.x, o.x, fmaf(wv.y, o.y, ta[bl]));
            }
        }
#pragma unroll
        for (int bl = 0; bl < KAB; bl++)
            g_t16[((size_t)(b0 + bl) * NCAP + i) * DIN + k] = __float2half_rn(ta[bl]);
    }
}

// ---------------- pass_route4: x slice fully SMEM-resident, x read ONCE ----------------
// grid (8 jchunk of 64, 64 b) = 512 CTAs, 512 threads, ~184 KB SMEM, 1 CTA/SM.
#define JT4    64
#define XPITB  2096                        // row pitch bytes (524 words ≡ 12 mod 32)
#define T_OFF4 (JT4 * XPITB)               // 134144
#define PL_OFF (T_OFF4 + 16 * XPITB)       // 167680
#define PLP    18                          // partial-logit pitch (floats)
#define C16_OFF4 (PL_OFF + 4 * 64 * PLP * 4)   // 186112
#define C16P4  72                          // c16 row pitch (halves)
#define PASS4_SMEM (C16_OFF4 + 16 * C16P4 * 2) // 188416

__global__ __launch_bounds__(512, 1) void pass_route4() {
    extern __shared__ char smb[];
    const uint32_t sb = smem_u32(smb);
    const int jc = blockIdx.x, b = blockIdx.y, tid = threadIdx.x;
    const int lane = tid & 31, w = tid >> 5;

    // one-shot load: x slice (64 x 1024 f16) + t16 (16 x 1024 f16)
    {
        const __half* xsrc = g_xh + ((size_t)(b * NIN + jc * JT4)) * DIN;
#pragma unroll 4
        for (int e = tid; e < 8192; e += 512) {
            const int r = e >> 7, c = e & 127;
            cp16(sb + r * XPITB + c * 16, xsrc + (size_t)r * DIN + c * 8);
        }
        const __half* tsrc = g_t16 + (size_t)b * NCAP * DIN;
#pragma unroll 2
        for (int e = tid; e < 2048; e += 512) {
            const int r = e >> 7, c = e & 127;
            cp16(sb + T_OFF4 + r * XPITB + c * 16, tsrc + (size_t)r * DIN + c * 8);
        }
        cp_commit();
    }
    asm volatile("cp.async.wait_group 0;\n" ::: "memory");
    __syncthreads();

    // ---- phase L: logits(64x16) = X @ t16^T; warp = (m-tile mt, k-quarter kq) ----
    const int mt = w >> 2, kq = w & 3;
    {
        const uint32_t a_base  = sb + (mt * 16 + (lane & 15)) * XPITB
                                 + ((lane >> 4) & 1) * 16 + kq * 512;
        const uint32_t bT_base = sb + T_OFF4 + (lane & 15) * XPITB
                                 + ((lane >> 4) & 1) * 16 + kq * 512;
        float la[2][4];
#pragma unroll
        for (int f = 0; f < 2; f++)
#pragma unroll
            for (int q = 0; q < 4; q++) la[f][q] = 0.f;
#pragma unroll
        for (int s = 0; s < 16; s++) {
            uint32_t af[4], bf[4];
            ldsm_x4(af, a_base + s * 32);
            ldsm_x4(bf, bT_base + s * 32);
            const uint32_t b0r[2] = {bf[0], bf[2]};
            const uint32_t b1r[2] = {bf[1], bf[3]};
            hmma(la[0], af, b0r);
            hmma(la[1], af, b1r);
        }
        float* pl = (float*)(smb + PL_OFF);
        const int jr = mt * 16 + (lane >> 2);
        const int ic = (lane & 3) * 2;
#pragma unroll
        for (int f = 0; f < 2; f++) {
            *(float2*)&pl[(kq * 64 + jr) * PLP + f * 8 + ic] =
                make_float2(la[f][0], la[f][1]);
            *(float2*)&pl[(kq * 64 + jr + 8) * PLP + f * 8 + ic] =
                make_float2(la[f][2], la[f][3]);
        }
    }
    __syncthreads();

    // ---- reduce k-quarters + softmax over 16 capsules -> c16 [i][j] f16 ----
    {
        const float* pl = (const float*)(smb + PL_OFF);
        __half* c16 = (__half*)(smb + C16_OFF4);
#pragma unroll
        for (int r = 0; r < 2; r++) {
            const int j = r * 32 + (tid >> 4), i = tid & 15;
            const float v = pl[(0 * 64 + j) * PLP + i] + pl[(1 * 64 + j) * PLP + i]
                          + pl[(2 * 64 + j) * PLP + i] + pl[(3 * 64 + j) * PLP + i];
            float m = v;
#pragma unroll
            for (int o = 1; o < 16; o <<= 1) m = fmaxf(m, __shfl_xor_sync(0xffffffffu, m, o));
            const float e = expf(v - m);
            float s = e;
#pragma unroll
            for (int o = 1; o < 16; o <<= 1) s += __shfl_xor_sync(0xffffffffu, s, o);
            c16[i * C16P4 + j] = __float2half_rn(e / s);
        }
    }
    __syncthreads();

    // ---- phase Y: y(16x1024) = c16(16x64) @ X(64x1024); warp = 64-col slab ----
    {
        uint32_t aj[4][4];
        const uint32_t ca = sb + C16_OFF4 + (lane & 15) * (C16P4 * 2) + ((lane >> 4) & 1) * 16;
#pragma unroll
        for (int s = 0; s < 4; s++) ldsm_x4(aj[s], ca + s * 32);

        float ya[8][4];
#pragma unroll
        for (int nf = 0; nf < 8; nf++)
#pragma unroll
            for (int q = 0; q < 4; q++) ya[nf][q] = 0.f;

#pragma unroll
        for (int s = 0; s < 4; s++) {
            const uint32_t rb = sb + (s * 16 + (lane & 15)) * XPITB + w * 128;
#pragma unroll
            for (int nf = 0; nf < 8; nf++) {
                uint32_t bf[2];
                ldsm_x2t(bf, rb + nf * 16);
                hmma(ya[nf], aj[s], bf);
            }
        }

        const int i0 = lane >> 2;
#pragma unroll
        for (int nf = 0; nf < 8; nf++) {
            const int kc = w * 64 + nf * 8 + (lane & 3) * 2;
            *(float2*)&g_ypart[jc][b][i0][kc]     = make_float2(ya[nf][0], ya[nf][1]);
            *(float2*)&g_ypart[jc][b][i0 + 8][kc] = make_float2(ya[nf][2], ya[nf][3]);
        }
    }
}

// ---------------- launch ----------------
extern "C" void kernel_launch(void* const* d_in, const int* in_sizes, int n_in,
                              void* d_out, int out_size) {
    const float* x = (const float*)d_in[0];
    const float* W = (const float*)d_in[1];
    if (in_sizes[0] == DIN * NCAP * DCAP && in_sizes[1] == (int)((size_t)BATCH * NIN * DIN)) {
        const float* t = x; x = W; W = t;
    }
    float* out = (float*)d_out;

    cudaFuncSetAttribute(kA2, cudaFuncAttributeMaxDynamicSharedMemorySize, KA_SMEM);
    cudaFuncSetAttribute(pass_route4, cudaFuncAttributeMaxDynamicSharedMemorySize, PASS4_SMEM);

    wh16_kernel<<<128, 256>>>(W);
    pass0<<<dim3(8, BATCH), 256>>>(x);
    kA2<<<dim3(NCAP, 8), 512, KA_SMEM>>>(out, 0);         // iter0: out0, t0
    pass_route4<<<dim3(8, BATCH), 512, PASS4_SMEM>>>();   // iter1: logits/softmax/y1
    kA2<<<dim3(NCAP, 8), 512, KA_SMEM>>>(out, 1);         // iter1: out1, t1
    pass_route4<<<dim3(8, BATCH), 512, PASS4_SMEM>>>();   // iter2: logits/softmax/y2
    kA2<<<dim3(NCAP, 8), 512, KA_SMEM>>>(out, 2);         // iter2: final out
}

// round 14
// speedup vs baseline: 1.4669x; 1.4669x over previous
#include <cuda_runtime.h>
#include <cuda_fp16.h>
#include <cstdint>

#define BATCH 64
#define NCAP  16
#define DCAP  64
#define NIN   512
#define DIN   1024

// ---------------- scratch (allocation-free: __device__ globals) ----------------
__device__ __half g_xh[(size_t)BATCH * NIN * DIN];       // 64 MB, x f16 [b][j][k]
__device__ __half g_wh16[(size_t)DIN * NCAP * DCAP];     // 2 MB, W f16 [k][n]
__device__ float  g_xsump[8][BATCH][DIN];                // 2 MB, partial x sums over j
__device__ __half g_t16[(size_t)BATCH * NCAP * DIN];     // 2 MB, t f16 [b][i][k]
__device__ float  g_ypart[4][BATCH][NCAP][DIN];          // 16 MB, y partials

// ---------------- helpers ----------------
__device__ __forceinline__ uint32_t smem_u32(const void* p) {
    uint32_t a;
    asm("{ .reg .u64 t; cvta.to.shared.u64 t, %1; cvt.u32.u64 %0, t; }" : "=r"(a) : "l"(p));
    return a;
}
__device__ __forceinline__ void cp16(uint32_t dst, const void* src) {
    asm volatile("cp.async.cg.shared.global [%0], [%1], 16;\n" :: "r"(dst), "l"(src));
}
__device__ __forceinline__ void cp_commit() { asm volatile("cp.async.commit_group;\n" ::: "memory"); }

__device__ __forceinline__ void hmma(float* d, const uint32_t* a, const uint32_t* b) {
    asm volatile(
        "mma.sync.aligned.m16n8k16.row.col.f32.f16.f16.f32 "
        "{%0,%1,%2,%3}, {%4,%5,%6,%7}, {%8,%9}, {%0,%1,%2,%3};\n"
        : "+f"(d[0]), "+f"(d[1]), "+f"(d[2]), "+f"(d[3])
        : "r"(a[0]), "r"(a[1]), "r"(a[2]), "r"(a[3]), "r"(b[0]), "r"(b[1]));
}
__device__ __forceinline__ void ldsm_x4(uint32_t* r, uint32_t addr) {
    asm volatile("ldmatrix.sync.aligned.m8n8.x4.shared.b16 {%0,%1,%2,%3}, [%4];"
                 : "=r"(r[0]), "=r"(r[1]), "=r"(r[2]), "=r"(r[3]) : "r"(addr));
}
__device__ __forceinline__ void ldsm_x2(uint32_t* r, uint32_t addr) {
    asm volatile("ldmatrix.sync.aligned.m8n8.x2.shared.b16 {%0,%1}, [%2];"
                 : "=r"(r[0]), "=r"(r[1]) : "r"(addr));
}
__device__ __forceinline__ void ldsm_x2t(uint32_t* r, uint32_t addr) {
    asm volatile("ldmatrix.sync.aligned.m8n8.x2.trans.shared.b16 {%0,%1}, [%2];"
                 : "=r"(r[0]), "=r"(r[1]) : "r"(addr));
}

// ---------------- prep: W f32 -> f16 ----------------
__global__ __launch_bounds__(256) void wh16_kernel(const float* __restrict__ W) {
    const size_t n4 = (size_t)DIN * 1024 / 4;
    for (size_t e = (size_t)blockIdx.x * blockDim.x + threadIdx.x; e < n4;
         e += (size_t)gridDim.x * blockDim.x) {
        float4 v = ((const float4*)W)[e];
        __half2* dst = (__half2*)g_wh16 + e * 2;
        dst[0] = __floats2half2_rn(v.x, v.y);
        dst[1] = __floats2half2_rn(v.z, v.w);
    }
}

// ---------------- pass0: xsum partials + x -> f16 ----------------
__global__ __launch_bounds__(256) void pass0(const float* __restrict__ X) {
    const int c = blockIdx.x, b = blockIdx.y, tid = threadIdx.x;
    const size_t rowbase = ((size_t)b * NIN + c * 64) * DIN;
    const float4* xp = (const float4*)(X + rowbase) + tid;
    uint2* xh = (uint2*)(g_xh + rowbase) + tid;
    float4 a = make_float4(0.f, 0.f, 0.f, 0.f);
#pragma unroll 4
    for (int j = 0; j < 64; j++) {
        const float4 v = xp[j * (DIN / 4)];
        a.x += v.x; a.y += v.y; a.z += v.z; a.w += v.w;
        const __half2 h0 = __floats2half2_rn(v.x, v.y);
        const __half2 h1 = __floats2half2_rn(v.z, v.w);
        uint2 u;
        u.x = *(const unsigned*)&h0;
        u.y = *(const unsigned*)&h1;
        xh[j * (DIN / 4)] = u;
    }
    ((float4*)g_xsump[c][b])[tid] = a;
}

// ---------------- kA3: y -> z = y@W_i (mma) -> squash -> t16 = out@W_i^T (mma) ----------------
// grid (16 i, 8 bgroup of 8) = 128 CTAs, 512 threads.
#define KAB 8
#define WPITB 144                          // W row pitch bytes (36 words = 4 mod 32)
#define YPITH 1032                         // y row pitch halves (2064 B, 516 words = 4 mod 32)
#define ZPIT  68                           // z partial pitch floats
#define OPITH 72                           // out16 row pitch halves (144 B)
#define KW_OFF 0
#define KY_OFF (DIN * WPITB)               // 147456
#define KZ_OFF (KY_OFF + 16 * YPITH * 2)   // +33024 = 180480
#define KO_OFF (KZ_OFF + 2 * 8 * ZPIT * 4) // +4352  = 184832
#define KA3_SMEM (KO_OFF + 16 * OPITH * 2) // +2304  = 187136

__global__ __launch_bounds__(512) void kA3(float* __restrict__ d_out, int stage) {
    extern __shared__ char smb[];
    const uint32_t sb = smem_u32(smb);
    __half* y16   = (__half*)(smb + KY_OFF);   // [16][1032] rows 8-15 zero
    float*  zp    = (float*)(smb + KZ_OFF);    // [2][8][68]
    __half* out16 = (__half*)(smb + KO_OFF);   // [16][72]  rows 8-15 zero

    const int i = blockIdx.x, bg = blockIdx.y, tid = threadIdx.x;
    const int b0 = bg * KAB;
    const int lane = tid & 31, w = tid >> 5;

    // stage W_i slice (1024 x 64 f16) at pitch 144B
    {
        const __half* src = g_wh16 + i * 64;
#pragma unroll 4
        for (int e = tid; e < 8192; e += 512) {
            const int k = e >> 3, c = e & 7;
            cp16(sb + k * WPITB + c * 16, src + (size_t)k * 1024 + c * 8);
        }
        cp_commit();
    }

    // build y16 (f16): rows 0-7 = y for 8 batches, rows 8-15 = 0
    for (int e = tid; e < 16 * DIN; e += 512) {
        const int r = e >> 10, k = e & 1023;
        float v = 0.f;
        if (r < 8) {
            if (stage == 0) {
#pragma unroll
                for (int p = 0; p < 8; p++) v += g_xsump[p][b0 + r][k];
                v *= (1.f / 16.f);
            } else {
#pragma unroll
                for (int p = 0; p < 4; p++) v += g_ypart[p][b0 + r][i][k];
            }
        }
        y16[r * YPITH + k] = __float2half_rn(v);
    }
    asm volatile("cp.async.wait_group 0;\n" ::: "memory");
    __syncthreads();

    // ---- z-phase: z(8x64) = y(8x1024) @ W(1024x64); warp = (kh, d-tile nt) ----
    {
        const int kh = w & 1, nt = w >> 1;
        float acc[4] = {0.f, 0.f, 0.f, 0.f};
        const uint32_t a_base = sb + KY_OFF + (uint32_t)(lane & 15) * (YPITH * 2)
                               + ((lane >> 4) & 1) * 16 + kh * 1024;
        const uint32_t b_row0 = (uint32_t)(kh * 512 + (lane & 15));
#pragma unroll
        for (int s = 0; s < 32; s++) {
            uint32_t af[4], bf[2];
            ldsm_x4(af, a_base + s * 32);
            ldsm_x2t(bf, sb + (b_row0 + s * 16) * WPITB + nt * 16);
            hmma(acc, af, bf);
        }
        // rows 0-7 valid (acc[0], acc[1]); rows 8-15 are zero padding
        const int bl = lane >> 2, dc = nt * 8 + (lane & 3) * 2;
        zp[(kh * 8 + bl) * ZPIT + dc]     = acc[0];
        zp[(kh * 8 + bl) * ZPIT + dc + 1] = acc[1];
    }
    __syncthreads();

    // ---- reduce 2 k-halves + squash; warps 0-7; warps 8-15 zero out16 rows 8-15 ----
    if (tid < 256) {
        const int bl = w;
        const float za = zp[(0 * 8 + bl) * ZPIT + 2 * lane]     + zp[(1 * 8 + bl) * ZPIT + 2 * lane];
        const float zb = zp[(0 * 8 + bl) * ZPIT + 2 * lane + 1] + zp[(1 * 8 + bl) * ZPIT + 2 * lane + 1];
        float sq = za * za + zb * zb;
#pragma unroll
        for (int o = 16; o; o >>= 1) sq += __shfl_xor_sync(0xffffffffu, sq, o);
        const float inv = 1.0f / sqrtf(sq + 1e-7f);
        const float ox = za * inv, oy = zb * inv;
        *(half2*)&out16[bl * OPITH + 2 * lane] = __floats2half2_rn(ox, oy);
        if (stage == 2) {
            float2* dp = (float2*)(d_out + ((size_t)(b0 + bl) * NCAP + i) * DCAP);
            dp[lane] = make_float2(ox, oy);
        }
    } else {
        const int idx = tid - 256;                  // 0..255
        const int r = 8 + (idx >> 5);
        *(half2*)&out16[r * OPITH + 2 * (idx & 31)] = __floats2half2_rn(0.f, 0.f);
    }
    __syncthreads();
    if (stage == 2) return;

    // ---- t-phase: t(8x1024) = out(8x64) @ W^T(64x1024); warp = 64-k slab ----
    {
        uint32_t af[4][4];
        const uint32_t oa = sb + KO_OFF + (uint32_t)(lane & 15) * (OPITH * 2)
                           + ((lane >> 4) & 1) * 16;
#pragma unroll
        for (int s = 0; s < 4; s++) ldsm_x4(af[s], oa + s * 32);

        float ta[8][4];
#pragma unroll
        for (int nt = 0; nt < 8; nt++)
#pragma unroll
            for (int q = 0; q < 4; q++) ta[nt][q] = 0.f;

#pragma unroll
        for (int s = 0; s < 4; s++) {
#pragma unroll
            for (int nt = 0; nt < 8; nt++) {
                uint32_t bf[2];
                ldsm_x2(bf, sb + (uint32_t)(w * 64 + nt * 8 + (lane & 7)) * WPITB
                            + ((lane >> 3) & 1) * 16 + s * 32);
                hmma(ta[nt], af[s], bf);
            }
        }

        const int bl = lane >> 2;
#pragma unroll
        for (int nt = 0; nt < 8; nt++) {
            const int k = w * 64 + nt * 8 + (lane & 3) * 2;
            *(half2*)&g_t16[((size_t)(b0 + bl) * NCAP + i) * DIN + k] =
                __floats2half2_rn(ta[nt][0], ta[nt][1]);
        }
    }
}

// ---------------- pass_route3: 3-buffer ring (round-11 version, best so far) ----------------
#define JT2   128
#define XPB   144
#define XBUF  (JT2 * XPB)                 // 18432
#define NBUF  3
#define T_OFF2 (NBUF * XBUF)              // 55296
#define TPB   2064
#define CF_OFF (T_OFF2 + 16 * TPB)        // 88320
#define CFP   20
#define C16_OFF (CF_OFF + JT2 * CFP * 4)  // 98560
#define C16P  136
#define PASS2_SMEM (C16_OFF + 16 * C16P * 2)  // 102912

__global__ __launch_bounds__(256, 2) void pass_route3() {
    extern __shared__ char smb[];
    const uint32_t sb = smem_u32(smb);
    const int jc = blockIdx.x, b = blockIdx.y, tid = threadIdx.x;
    const int lane = tid & 31, w = tid >> 5;
    const int j0 = jc * JT2;

    {
        const __half* src = g_t16 + (size_t)b * NCAP * DIN;
        for (int e = tid; e < 2048; e += 256) {
            const int r = e >> 7, c = e & 127;
            cp16(sb + T_OFF2 + r * TPB + c * 16, src + (size_t)r * DIN + c * 8);
        }
        cp_commit();
    }
    auto load_panel = [&](int p) {
        const uint32_t base = sb + (uint32_t)(p % NBUF) * XBUF;
        const __half* src = g_xh + ((size_t)(b * NIN + j0)) * DIN + p * 64;
        for (int e = tid; e < 1024; e += 256) {
            const int j = e >> 3, c = e & 7;
            cp16(base + j * XPB + c * 16, src + (size_t)j * DIN + c * 8);
        }
        cp_commit();
    };
    load_panel(0);
    load_panel(1);

    const uint32_t a_base  = sb + (w * 16 + (lane & 15)) * XPB + ((lane >> 4) & 1) * 16;
    const uint32_t bT_base = sb + T_OFF2 + (lane & 15) * TPB + ((lane >> 4) & 1) * 16;

    float la[2][4];
#pragma unroll
    for (int f = 0; f < 2; f++)
#pragma unroll
        for (int q = 0; q < 4; q++) la[f][q] = 0.f;

    for (int p = 0; p < 16; p++) {
        if (p < 14) asm volatile("cp.async.wait_group 1;\n" ::: "memory");
        else        asm volatile("cp.async.wait_group 0;\n" ::: "memory");
        __syncthreads();
        if (p + 2 < 16) load_panel(p + 2);
        const uint32_t xb = (uint32_t)(p % NBUF) * XBUF;
#pragma unroll
        for (int s = 0; s < 4; s++) {
            uint32_t af[4], bf[4];
            ldsm_x4(af, a_base + xb + s * 32);
            ldsm_x4(bf, bT_base + (p * 4 + s) * 32);
            const uint32_t b0r[2] = {bf[0], bf[2]};
            const uint32_t b1r[2] = {bf[1], bf[3]};
            hmma(la[0], af, b0r);
            hmma(la[1], af, b1r);
        }
    }

    {
        float* cf = (float*)(smb + CF_OFF);
        const int jr = w * 16 + (lane >> 2);
        const int ic = (lane & 3) * 2;
#pragma unroll
        for (int f = 0; f < 2; f++) {
            *(float2*)&cf[jr * CFP + f * 8 + ic]       = make_float2(la[f][0], la[f][1]);
            *(float2*)&cf[(jr + 8) * CFP + f * 8 + ic] = make_float2(la[f][2], la[f][3]);
        }
    }
    __syncthreads();
    load_panel(0);
    load_panel(1);

    {
        const float* cf  = (const float*)(smb + CF_OFF);
        __half* c16 = (__half*)(smb + C16_OFF);
#pragma unroll
        for (int it = 0; it < 8; it++) {
            const int j = it * 16 + (tid >> 4), ii = tid & 15;
            const float v = cf[j * CFP + ii];
            float m = v;
#pragma unroll
            for (int o = 1; o < 16; o <<= 1) m = fmaxf(m, __shfl_xor_sync(0xffffffffu, m, o));
            const float e = expf(v - m);
            float s = e;
#pragma unroll
            for (int o = 1; o < 16; o <<= 1) s += __shfl_xor_sync(0xffffffffu, s, o);
            c16[ii * C16P + j] = __float2half_rn(e / s);
        }
    }
    __syncthreads();

    uint32_t aj[8][4];
    {
        const uint32_t ca = sb + C16_OFF + (lane & 15) * (C16P * 2) + ((lane >> 4) & 1) * 16;
#pragma unroll
        for (int js = 0; js < 8; js++) ldsm_x4(aj[js], ca + js * 32);
    }

    const uint32_t bx_base = sb + (lane & 15) * XPB + w * 16;
    for (int p = 0; p < 16; p++) {
        if (p < 14) asm volatile("cp.async.wait_group 1;\n" ::: "memory");
        else        asm volatile("cp.async.wait_group 0;\n" ::: "memory");
        __syncthreads();
        if (p + 2 < 16) load_panel(p + 2);
        const uint32_t xb = (uint32_t)(p % NBUF) * XBUF;
        float ya[4] = {0.f, 0.f, 0.f, 0.f};
#pragma unroll
        for (int js = 0; js < 8; js++) {
            uint32_t bf[2];
            ldsm_x2t(bf, bx_base + xb + js * 16 * XPB);
            hmma(ya, aj[js], bf);
        }
        const int i0 = lane >> 2;
        const int kc = p * 64 + w * 8 + (lane & 3) * 2;
        *(float2*)&g_ypart[jc][b][i0][kc]     = make_float2(ya[0], ya[1]);
        *(float2*)&g_ypart[jc][b][i0 + 8][kc] = make_float2(ya[2], ya[3]);
    }
}

// ---------------- launch ----------------
extern "C" void kernel_launch(void* const* d_in, const int* in_sizes, int n_in,
                              void* d_out, int out_size) {
    const float* x = (const float*)d_in[0];
    const float* W = (const float*)d_in[1];
    if (in_sizes[0] == DIN * NCAP * DCAP && in_sizes[1] == (int)((size_t)BATCH * NIN * DIN)) {
        const float* t = x; x = W; W = t;
    }
    float* out = (float*)d_out;

    cudaFuncSetAttribute(kA3, cudaFuncAttributeMaxDynamicSharedMemorySize, KA3_SMEM);
    cudaFuncSetAttribute(pass_route3, cudaFuncAttributeMaxDynamicSharedMemorySize, PASS2_SMEM);

    wh16_kernel<<<128, 256>>>(W);
    pass0<<<dim3(8, BATCH), 256>>>(x);
    kA3<<<dim3(NCAP, 8), 512, KA3_SMEM>>>(out, 0);        // iter0: out0, t0
    pass_route3<<<dim3(4, BATCH), 256, PASS2_SMEM>>>();   // iter1: logits/softmax/y1
    kA3<<<dim3(NCAP, 8), 512, KA3_SMEM>>>(out, 1);        // iter1: out1, t1
    pass_route3<<<dim3(4, BATCH), 256, PASS2_SMEM>>>();   // iter2: logits/softmax/y2
    kA3<<<dim3(NCAP, 8), 512, KA3_SMEM>>>(out, 2);        // iter2: final out
}